// round 13
// baseline (speedup 1.0000x reference)
#include <cuda_runtime.h>

// Problem constants
#define NCHIP   8
#define SEQ     2048
#define TOPK    8
#define HID     1024
#define NEXP    64
#define MAXTOK  2560
#define NPC     (SEQ * TOPK)          // 16384 assignments per chip
#define NTOT    (NCHIP * NPC)         // 131072 assignments total
#define NROWS   (NEXP * MAXTOK)       // 163840 output rows
#define METAL   8
#define RPB     16                    // rows per gather block (MAXTOK % RPB == 0)

// Output layout (flattened concat, float32):
//   [0, NROWS*HID)                       dispatched
//   [NROWS*HID, NROWS*HID + NROWS*8)     metadata
//   [... , +64)                          tokens_per_expert (value-cast to float)
#define DISP_ELEMS   ((size_t)NROWS * HID)          // 167772160
#define META_OFF     DISP_ELEMS
#define META_ELEMS   ((size_t)NROWS * METAL)        // 1310720
#define TPE_OFF      (META_OFF + META_ELEMS)        // 169082880

// Scratch (static device globals; no allocation allowed)
__device__ int g_counts[NCHIP * NEXP];
__device__ int g_off[NCHIP * NEXP];
__device__ int g_total[NEXP];
__device__ int g_rank[NTOT];
__device__ int g_src[NROWS];

// ---------------------------------------------------------------------------
// Kernel A: per-chip scan-order ranks + per-(chip,expert) counts.
// grid = 8 (one block per chip), block = 128. Deterministic chunked histogram
// + per-expert exclusive scan (matches jnp stable-argsort rank semantics).
// ---------------------------------------------------------------------------
__global__ void k_rank(const int* __restrict__ idx) {
    __shared__ int cnt[128 * NEXP];   // 32 KB
    const int c = blockIdx.x;
    const int t = threadIdx.x;
    const int* ci = idx + c * NPC;
    int* my = cnt + t * NEXP;

    #pragma unroll
    for (int e = 0; e < NEXP; e++) my[e] = 0;

    const int n0 = t * 128;
    #pragma unroll 4
    for (int i = 0; i < 128; i++) my[ci[n0 + i]]++;
    __syncthreads();

    if (t < NEXP) {
        int run = 0;
        for (int b = 0; b < 128; b++) {
            int v = cnt[b * NEXP + t];
            cnt[b * NEXP + t] = run;
            run += v;
        }
        g_counts[c * NEXP + t] = run;
    }
    __syncthreads();

    #pragma unroll 4
    for (int i = 0; i < 128; i++) {
        int e = ci[n0 + i];
        g_rank[c * NPC + n0 + i] = my[e]++;
    }
}

// ---------------------------------------------------------------------------
// Kernel B: exclusive prefix over chips -> chip offsets; totals ->
// g_total + tokens_per_expert (value-converted to float). 1 block, 64 threads.
// ---------------------------------------------------------------------------
__global__ void k_scan(float* __restrict__ out) {
    const int e = threadIdx.x;   // 0..63, flat (chip*8 + local) order
    int run = 0;
    for (int c = 0; c < NCHIP; c++) {
        g_off[c * NEXP + e] = run;
        run += g_counts[c * NEXP + e];
    }
    g_total[e] = run;
    out[TPE_OFF + e] = (float)run;
}

// ---------------------------------------------------------------------------
// Kernel C: scatter assignment ids into the row table. dest slots are unique
// by construction (plain stores). Filled slots per expert are exactly
// [0, g_total[e]) so no -1 init pass is needed.
// ---------------------------------------------------------------------------
__global__ void k_scatter(const int* __restrict__ idx) {
    int a = blockIdx.x * blockDim.x + threadIdx.x;
    if (a >= NTOT) return;
    int c = a >> 14;               // a / NPC
    int e = idx[a];
    int dest = e * MAXTOK + g_off[c * NEXP + e] + g_rank[a];
    if (dest < NROWS) g_src[dest] = a;
}

// ---------------------------------------------------------------------------
// Kernel D: the big gather, MLP-optimized. Grid = (MAXTOK/RPB, NEXP), block
// 256. Prologue: threads 0..RPB-1 resolve g_src for RPB rows into shared and
// write the metadata rows. Main loop: each thread copies one float4 per row,
// fully unrolled over RPB rows -> RPB independent LDG.128s in flight per
// thread (front-batched by ptxas), hiding L2/DRAM latency and saturating BW.
// Output stores use __stcs (evict-first) so the 645MB write stream does not
// evict x (64MB) from L2, keeping the 8x token re-reads L2-resident.
// ---------------------------------------------------------------------------
__global__ void __launch_bounds__(256) k_gather(const float* __restrict__ x,
                                                const float* __restrict__ w,
                                                float* __restrict__ out) {
    __shared__ int s_row[RPB];          // x row index (c*SEQ+s), or -1 = empty

    const int e     = blockIdx.y;
    const int base  = blockIdx.x * RPB;         // slot base within expert
    const int rbase = e * MAXTOK + base;        // global row base
    const int t     = threadIdx.x;

    if (t < RPB) {
        const int slot = base + t;
        const int r    = rbase + t;
        int rowx = -1;
        float4* mrow = reinterpret_cast<float4*>(out + META_OFF + (size_t)r * METAL);
        if (slot < g_total[e]) {
            const int a = g_src[r];
            const int c = a >> 14;
            const int n = a & (NPC - 1);
            const int s = n >> 3;
            const int k = n & 7;
            rowx = c * SEQ + s;
            const float wt = __ldg(&w[rowx * TOPK + k]);
            __stcs(mrow,     make_float4((float)c, (float)s, (float)k, (float)e));
            __stcs(mrow + 1, make_float4(wt, 0.f, 0.f, 0.f));
        } else {
            __stcs(mrow,     make_float4(-1.f, -1.f, -1.f, -1.f));
            __stcs(mrow + 1, make_float4(-1.f, -1.f, -1.f, -1.f));
        }
        s_row[t] = rowx;
    }
    __syncthreads();

    const float4* __restrict__ x4 = reinterpret_cast<const float4*>(x);
    float4* __restrict__ dst = reinterpret_cast<float4*>(out) + (size_t)rbase * (HID / 4);
    const float4 z = make_float4(0.f, 0.f, 0.f, 0.f);

    #pragma unroll
    for (int i = 0; i < RPB; i++) {
        const int rowx = s_row[i];
        float4 v = z;
        if (rowx >= 0) v = __ldg(&x4[(size_t)rowx * (HID / 4) + t]);
        __stcs(&dst[(size_t)i * (HID / 4) + t], v);
    }
}

// ---------------------------------------------------------------------------
extern "C" void kernel_launch(void* const* d_in, const int* in_sizes, int n_in,
                              void* d_out, int out_size) {
    const float* x   = (const float*)d_in[0];   // (8,2048,1024) f32
    const float* wts = (const float*)d_in[1];   // (8,2048,8) f32
    const int*   idx = (const int*)d_in[2];     // (8,2048,8) i32
    float* out = (float*)d_out;

    k_rank<<<NCHIP, 128>>>(idx);
    k_scan<<<1, NEXP>>>(out);
    k_scatter<<<(NTOT + 255) / 256, 256>>>(idx);
    dim3 g(MAXTOK / RPB, NEXP);
    k_gather<<<g, 256>>>(x, wts, out);
}

// round 14
// speedup vs baseline: 1.0043x; 1.0043x over previous
#include <cuda_runtime.h>

// Problem constants
#define NCHIP   8
#define SEQ     2048
#define TOPK    8
#define HID     1024
#define NEXP    64
#define MAXTOK  2560
#define NPC     (SEQ * TOPK)          // 16384 assignments per chip
#define NTOT    (NCHIP * NPC)         // 131072 assignments total
#define NROWS   (NEXP * MAXTOK)       // 163840 output rows
#define METAL   8
#define RPB     16                    // rows per gather block (MAXTOK % RPB == 0)

// Output layout (flattened concat, float32):
//   [0, NROWS*HID)                       dispatched
//   [NROWS*HID, NROWS*HID + NROWS*8)     metadata
//   [... , +64)                          tokens_per_expert (value-cast to float)
#define DISP_ELEMS   ((size_t)NROWS * HID)          // 167772160
#define META_OFF     DISP_ELEMS
#define META_ELEMS   ((size_t)NROWS * METAL)        // 1310720
#define TPE_OFF      (META_OFF + META_ELEMS)        // 169082880

// Scratch (static device globals; no allocation allowed)
__device__ int g_counts[NCHIP * NEXP];
__device__ int g_off[NCHIP * NEXP];
__device__ int g_total[NEXP];
__device__ int g_rank[NTOT];
__device__ int g_src[NROWS];

// ---------------------------------------------------------------------------
// Kernel A: per-chip scan-order ranks + per-(chip,expert) counts.
// grid = 8 (one block per chip), block = 128. Deterministic chunked histogram
// + per-expert exclusive scan (matches jnp stable-argsort rank semantics).
// ---------------------------------------------------------------------------
__global__ void k_rank(const int* __restrict__ idx) {
    __shared__ int cnt[128 * NEXP];   // 32 KB
    const int c = blockIdx.x;
    const int t = threadIdx.x;
    const int* ci = idx + c * NPC;
    int* my = cnt + t * NEXP;

    #pragma unroll
    for (int e = 0; e < NEXP; e++) my[e] = 0;

    const int n0 = t * 128;
    #pragma unroll 4
    for (int i = 0; i < 128; i++) my[ci[n0 + i]]++;
    __syncthreads();

    if (t < NEXP) {
        int run = 0;
        for (int b = 0; b < 128; b++) {
            int v = cnt[b * NEXP + t];
            cnt[b * NEXP + t] = run;
            run += v;
        }
        g_counts[c * NEXP + t] = run;
    }
    __syncthreads();

    #pragma unroll 4
    for (int i = 0; i < 128; i++) {
        int e = ci[n0 + i];
        g_rank[c * NPC + n0 + i] = my[e]++;
    }
}

// ---------------------------------------------------------------------------
// Kernel B: exclusive prefix over chips -> chip offsets; totals ->
// g_total + tokens_per_expert (value-converted to float). 1 block, 64 threads.
// ---------------------------------------------------------------------------
__global__ void k_scan(float* __restrict__ out) {
    const int e = threadIdx.x;   // 0..63, flat (chip*8 + local) order
    int run = 0;
    for (int c = 0; c < NCHIP; c++) {
        g_off[c * NEXP + e] = run;
        run += g_counts[c * NEXP + e];
    }
    g_total[e] = run;
    out[TPE_OFF + e] = (float)run;
}

// ---------------------------------------------------------------------------
// Kernel C: scatter assignment ids into the row table. dest slots are unique
// by construction (plain stores). Filled slots per expert are exactly
// [0, g_total[e]) so no -1 init pass is needed.
// ---------------------------------------------------------------------------
__global__ void k_scatter(const int* __restrict__ idx) {
    int a = blockIdx.x * blockDim.x + threadIdx.x;
    if (a >= NTOT) return;
    int c = a >> 14;               // a / NPC
    int e = idx[a];
    int dest = e * MAXTOK + g_off[c * NEXP + e] + g_rank[a];
    if (dest < NROWS) g_src[dest] = a;
}

// ---------------------------------------------------------------------------
// Kernel D: the big gather, MLP-optimized. Grid = (MAXTOK/RPB, NEXP), block
// 256. Prologue: threads 0..RPB-1 resolve g_src for RPB rows into shared and
// write the metadata rows. Main loop: each thread copies one float4 per row,
// fully unrolled over RPB rows -> RPB independent LDG.128s in flight per
// thread (front-batched by ptxas), hiding L2/DRAM latency and saturating BW.
// Output stores use __stcs (evict-first) so the 645MB write stream does not
// evict x (64MB) from L2, keeping the 8x token re-reads L2-resident.
// ---------------------------------------------------------------------------
__global__ void __launch_bounds__(256) k_gather(const float* __restrict__ x,
                                                const float* __restrict__ w,
                                                float* __restrict__ out) {
    __shared__ int s_row[RPB];          // x row index (c*SEQ+s), or -1 = empty

    const int e     = blockIdx.y;
    const int base  = blockIdx.x * RPB;         // slot base within expert
    const int rbase = e * MAXTOK + base;        // global row base
    const int t     = threadIdx.x;

    if (t < RPB) {
        const int slot = base + t;
        const int r    = rbase + t;
        int rowx = -1;
        float4* mrow = reinterpret_cast<float4*>(out + META_OFF + (size_t)r * METAL);
        if (slot < g_total[e]) {
            const int a = g_src[r];
            const int c = a >> 14;
            const int n = a & (NPC - 1);
            const int s = n >> 3;
            const int k = n & 7;
            rowx = c * SEQ + s;
            const float wt = __ldg(&w[rowx * TOPK + k]);
            __stcs(mrow,     make_float4((float)c, (float)s, (float)k, (float)e));
            __stcs(mrow + 1, make_float4(wt, 0.f, 0.f, 0.f));
        } else {
            __stcs(mrow,     make_float4(-1.f, -1.f, -1.f, -1.f));
            __stcs(mrow + 1, make_float4(-1.f, -1.f, -1.f, -1.f));
        }
        s_row[t] = rowx;
    }
    __syncthreads();

    const float4* __restrict__ x4 = reinterpret_cast<const float4*>(x);
    float4* __restrict__ dst = reinterpret_cast<float4*>(out) + (size_t)rbase * (HID / 4);
    const float4 z = make_float4(0.f, 0.f, 0.f, 0.f);

    #pragma unroll
    for (int i = 0; i < RPB; i++) {
        const int rowx = s_row[i];
        float4 v = z;
        if (rowx >= 0) v = __ldg(&x4[(size_t)rowx * (HID / 4) + t]);
        __stcs(&dst[(size_t)i * (HID / 4) + t], v);
    }
}

// ---------------------------------------------------------------------------
extern "C" void kernel_launch(void* const* d_in, const int* in_sizes, int n_in,
                              void* d_out, int out_size) {
    const float* x   = (const float*)d_in[0];   // (8,2048,1024) f32
    const float* wts = (const float*)d_in[1];   // (8,2048,8) f32
    const int*   idx = (const int*)d_in[2];     // (8,2048,8) i32
    float* out = (float*)d_out;

    k_rank<<<NCHIP, 128>>>(idx);
    k_scan<<<1, NEXP>>>(out);
    k_scatter<<<(NTOT + 255) / 256, 256>>>(idx);
    dim3 g(MAXTOK / RPB, NEXP);
    k_gather<<<g, 256>>>(x, wts, out);
}

// round 15
// speedup vs baseline: 1.1966x; 1.1915x over previous
#include <cuda_runtime.h>

// Problem constants
#define NCHIP   8
#define SEQ     2048
#define TOPK    8
#define HID     1024
#define NEXP    64
#define MAXTOK  2560
#define NPC     (SEQ * TOPK)          // 16384 assignments per chip
#define NTOT    (NCHIP * NPC)         // 131072 assignments total
#define NROWS   (NEXP * MAXTOK)       // 163840 output rows
#define METAL   8
#define RPB     16                    // rows per gather block (MAXTOK % RPB == 0)

// Output layout (flattened concat, float32):
//   [0, NROWS*HID)                       dispatched
//   [NROWS*HID, NROWS*HID + NROWS*8)     metadata
//   [... , +64)                          tokens_per_expert (value-cast to float)
#define DISP_ELEMS   ((size_t)NROWS * HID)          // 167772160
#define META_OFF     DISP_ELEMS
#define META_ELEMS   ((size_t)NROWS * METAL)        // 1310720
#define TPE_OFF      (META_OFF + META_ELEMS)        // 169082880

// Scratch (static device globals; no allocation allowed)
__device__ int g_counts[NCHIP * NEXP];
__device__ int g_total[NEXP];
__device__ int g_rank[NTOT];
__device__ int g_src[NROWS];

// ---------------------------------------------------------------------------
// Kernel A: per-chip scan-order ranks + per-(chip,expert) counts.
// grid = 8 (one block per chip), block = 128. Deterministic chunked histogram
// + per-expert exclusive scan (matches jnp stable-argsort rank semantics).
// ---------------------------------------------------------------------------
__global__ void k_rank(const int* __restrict__ idx) {
    __shared__ int cnt[128 * NEXP];   // 32 KB
    const int c = blockIdx.x;
    const int t = threadIdx.x;
    const int* ci = idx + c * NPC;
    int* my = cnt + t * NEXP;

    #pragma unroll
    for (int e = 0; e < NEXP; e++) my[e] = 0;

    const int n0 = t * 128;
    #pragma unroll 4
    for (int i = 0; i < 128; i++) my[ci[n0 + i]]++;
    __syncthreads();

    if (t < NEXP) {
        int run = 0;
        for (int b = 0; b < 128; b++) {
            int v = cnt[b * NEXP + t];
            cnt[b * NEXP + t] = run;
            run += v;
        }
        g_counts[c * NEXP + t] = run;
    }
    __syncthreads();

    #pragma unroll 4
    for (int i = 0; i < 128; i++) {
        int e = ci[n0 + i];
        g_rank[c * NPC + n0 + i] = my[e]++;
    }
}

// ---------------------------------------------------------------------------
// Kernel C: scatter assignment ids into the row table, with the chip-offset
// prefix scan fused in (each block recomputes the tiny 8x64 exclusive scan
// from g_counts in smem — cheaper than a separate kernel launch). Block 0
// also publishes g_total and tokens_per_expert (value-cast to float).
// dest slots are unique by construction (plain stores). Filled slots per
// expert are exactly [0, g_total[e]) so no -1 init pass is needed.
// grid = NTOT/256 = 512, block = 256.
// ---------------------------------------------------------------------------
__global__ void __launch_bounds__(256) k_scatter(const int* __restrict__ idx,
                                                 float* __restrict__ out) {
    __shared__ int s_off[NCHIP * NEXP];
    const int t = threadIdx.x;

    if (t < NEXP) {
        int run = 0;
        #pragma unroll
        for (int c = 0; c < NCHIP; c++) {
            s_off[c * NEXP + t] = run;
            run += g_counts[c * NEXP + t];
        }
        if (blockIdx.x == 0) {
            g_total[t] = run;
            out[TPE_OFF + t] = (float)run;
        }
    }
    __syncthreads();

    const int a = blockIdx.x * 256 + t;          // NTOT == 512*256 exactly
    const int c = a >> 14;                       // a / NPC
    const int e = idx[a];
    const int dest = e * MAXTOK + s_off[c * NEXP + e] + g_rank[a];
    if (dest < NROWS) g_src[dest] = a;
}

// ---------------------------------------------------------------------------
// Kernel D: the big gather, MLP + locality optimized.
// Grid = (NEXP, MAXTOK/RPB)  — expert-major block order, so the concurrent
// wave covers the SAME slot range across ALL 64 experts. A token's 8 copies
// land at nearly identical slot indices in their 8 experts (chip offsets are
// uniform), so all copies are processed within one wave: x row is read from
// DRAM once and L2-served for the other 7 — DRAM reads drop to compulsory.
// Prologue: threads 0..RPB-1 resolve g_src for RPB rows into shared and
// write the metadata rows. Main loop: each thread copies one float4 per row,
// fully unrolled over RPB rows -> 16 independent LDG.128s in flight per
// thread. Output stores use __stcs (evict-first) to keep x L2-resident.
// ---------------------------------------------------------------------------
__global__ void __launch_bounds__(256) k_gather(const float* __restrict__ x,
                                                const float* __restrict__ w,
                                                float* __restrict__ out) {
    __shared__ int s_row[RPB];          // x row index (c*SEQ+s), or -1 = empty

    const int e     = blockIdx.x;
    const int base  = blockIdx.y * RPB;         // slot base within expert
    const int rbase = e * MAXTOK + base;        // global row base
    const int t     = threadIdx.x;

    if (t < RPB) {
        const int slot = base + t;
        const int r    = rbase + t;
        int rowx = -1;
        float4* mrow = reinterpret_cast<float4*>(out + META_OFF + (size_t)r * METAL);
        if (slot < g_total[e]) {
            const int a = g_src[r];
            const int c = a >> 14;
            const int n = a & (NPC - 1);
            const int s = n >> 3;
            const int k = n & 7;
            rowx = c * SEQ + s;
            const float wt = __ldg(&w[rowx * TOPK + k]);
            __stcs(mrow,     make_float4((float)c, (float)s, (float)k, (float)e));
            __stcs(mrow + 1, make_float4(wt, 0.f, 0.f, 0.f));
        } else {
            __stcs(mrow,     make_float4(-1.f, -1.f, -1.f, -1.f));
            __stcs(mrow + 1, make_float4(-1.f, -1.f, -1.f, -1.f));
        }
        s_row[t] = rowx;
    }
    __syncthreads();

    const float4* __restrict__ x4 = reinterpret_cast<const float4*>(x);
    float4* __restrict__ dst = reinterpret_cast<float4*>(out) + (size_t)rbase * (HID / 4);
    const float4 z = make_float4(0.f, 0.f, 0.f, 0.f);

    #pragma unroll
    for (int i = 0; i < RPB; i++) {
        const int rowx = s_row[i];
        float4 v = z;
        if (rowx >= 0) v = __ldg(&x4[(size_t)rowx * (HID / 4) + t]);
        __stcs(&dst[(size_t)i * (HID / 4) + t], v);
    }
}

// ---------------------------------------------------------------------------
extern "C" void kernel_launch(void* const* d_in, const int* in_sizes, int n_in,
                              void* d_out, int out_size) {
    const float* x   = (const float*)d_in[0];   // (8,2048,1024) f32
    const float* wts = (const float*)d_in[1];   // (8,2048,8) f32
    const int*   idx = (const int*)d_in[2];     // (8,2048,8) i32
    float* out = (float*)d_out;

    k_rank<<<NCHIP, 128>>>(idx);
    k_scatter<<<NTOT / 256, 256>>>(idx, out);
    dim3 g(NEXP, MAXTOK / RPB);
    k_gather<<<g, 256>>>(x, wts, out);
}

// round 16
// speedup vs baseline: 1.4783x; 1.2353x over previous
#include <cuda_runtime.h>

// Problem constants
#define NCHIP   8
#define SEQ     2048
#define TOPK    8
#define HID     1024
#define NEXP    64
#define MAXTOK  2560
#define NPC     (SEQ * TOPK)          // 16384 assignments per chip
#define NTOT    (NCHIP * NPC)         // 131072 assignments total
#define NROWS   (NEXP * MAXTOK)       // 163840 output rows
#define METAL   8
#define RPB     16                    // rows per gather block
#define NWARPSEQ (NTOT / 32)          // 4096 scan-ordered warps

// Output layout (flattened concat, float32):
#define DISP_ELEMS   ((size_t)NROWS * HID)          // 167772160
#define META_OFF     DISP_ELEMS
#define META_ELEMS   ((size_t)NROWS * METAL)        // 1310720
#define TPE_OFF      (META_OFF + META_ELEMS)        // 169082880

// Scratch (static device globals; no allocation allowed)
__device__ int g_wcnt[NWARPSEQ * NEXP];   // per-warp per-expert counts (1MB)
__device__ int g_woff[NWARPSEQ * NEXP];   // exclusive scan of the above (1MB)
__device__ int g_total[NEXP];
__device__ int g_src[NROWS];

// ---------------------------------------------------------------------------
// Phase 1: per-warp expert histograms via __match_any_sync. Each warp owns 32
// consecutive assignments (scan order); the group leader writes popc(mask).
// No atomics, no serial smem chains. grid = NTOT/256 = 512, block = 256.
// ---------------------------------------------------------------------------
__global__ void __launch_bounds__(256) k_hist(const int* __restrict__ idx) {
    const int a    = blockIdx.x * 256 + threadIdx.x;
    const int lane = threadIdx.x & 31;
    const int seq  = a >> 5;                       // global warp index
    int* row = g_wcnt + seq * NEXP;

    const int e = idx[a];
    row[lane]      = 0;                            // zero this warp's 64-entry row
    row[lane + 32] = 0;
    __syncwarp();

    const unsigned mask = __match_any_sync(0xffffffffu, e);
    if (lane == (__ffs(mask) - 1)) row[e] = __popc(mask);
}

// ---------------------------------------------------------------------------
// Phase 2: per-expert exclusive scan over the 4096 scan-ordered warp counts.
// This IS the combined (chip offset + within-chip rank base) computation:
// global slot base for warp seq, expert e. Also emits g_total and the
// tokens_per_expert output (value-cast to float, flat expert order).
// grid = 64 (one block per expert), block = 128 (32 values per thread).
// ---------------------------------------------------------------------------
__global__ void __launch_bounds__(128) k_scan(float* __restrict__ out) {
    const int e = blockIdx.x;
    const int t = threadIdx.x;
    const int lane = t & 31, wid = t >> 5;

    int vals[32];
    int sum = 0;
    const int base = (t * 32) * NEXP + e;
    #pragma unroll
    for (int i = 0; i < 32; i++) { vals[i] = g_wcnt[base + i * NEXP]; sum += vals[i]; }

    // inclusive warp scan of per-thread sums
    int s = sum;
    #pragma unroll
    for (int o = 1; o < 32; o <<= 1) {
        int v = __shfl_up_sync(0xffffffffu, s, o);
        if (lane >= o) s += v;
    }
    __shared__ int wsum[4];
    if (lane == 31) wsum[wid] = s;
    __syncthreads();
    int wpre = 0;
    #pragma unroll
    for (int wme = 0; wme < 4; wme++) if (wme < wid) wpre += wsum[wme];

    int excl = wpre + s - sum;                      // exclusive prefix, this thread
    #pragma unroll
    for (int i = 0; i < 32; i++) { g_woff[base + i * NEXP] = excl; excl += vals[i]; }

    if (t == 127) { g_total[e] = excl; out[TPE_OFF + e] = (float)excl; }
}

// ---------------------------------------------------------------------------
// Phase 3: scatter assignment ids into the row table. Intra-warp scan-order
// rank from match_any + popc(lanemask_lt); slot base from g_woff. dest slots
// are unique by construction. Filled slots per expert are exactly
// [0, g_total[e]) so no -1 init pass is needed. mode="drop" == dest bound.
// grid = 512, block = 256.
// ---------------------------------------------------------------------------
__global__ void __launch_bounds__(256) k_scatter(const int* __restrict__ idx) {
    const int a    = blockIdx.x * 256 + threadIdx.x;
    const int lane = threadIdx.x & 31;
    const int e    = idx[a];
    const unsigned mask = __match_any_sync(0xffffffffu, e);
    const int rank = __popc(mask & ((1u << lane) - 1u));
    const int dest = e * MAXTOK + g_woff[(a >> 5) * NEXP + e] + rank;
    if (dest < NROWS) g_src[dest] = a;
}

// ---------------------------------------------------------------------------
// Phase 4: the big gather, MLP + locality optimized.
// Grid = (NEXP, MAXTOK/RPB) — expert-major block order so the concurrent wave
// covers the same slot range across all 64 experts; a token's 8 copies sit at
// near-identical slots, so x is DRAM-read once and L2-served 7x.
// Prologue resolves g_src for RPB rows + writes metadata; main loop issues
// 16 independent LDG.128s per thread. __stcs keeps the write stream from
// evicting x in L2.
// ---------------------------------------------------------------------------
__global__ void __launch_bounds__(256) k_gather(const float* __restrict__ x,
                                                const float* __restrict__ w,
                                                float* __restrict__ out) {
    __shared__ int s_row[RPB];          // x row index (c*SEQ+s), or -1 = empty

    const int e     = blockIdx.x;
    const int base  = blockIdx.y * RPB;
    const int rbase = e * MAXTOK + base;
    const int t     = threadIdx.x;

    if (t < RPB) {
        const int slot = base + t;
        const int r    = rbase + t;
        int rowx = -1;
        float4* mrow = reinterpret_cast<float4*>(out + META_OFF + (size_t)r * METAL);
        if (slot < g_total[e]) {
            const int a = g_src[r];
            const int c = a >> 14;
            const int n = a & (NPC - 1);
            const int s = n >> 3;
            const int k = n & 7;
            rowx = c * SEQ + s;
            const float wt = __ldg(&w[rowx * TOPK + k]);
            __stcs(mrow,     make_float4((float)c, (float)s, (float)k, (float)e));
            __stcs(mrow + 1, make_float4(wt, 0.f, 0.f, 0.f));
        } else {
            __stcs(mrow,     make_float4(-1.f, -1.f, -1.f, -1.f));
            __stcs(mrow + 1, make_float4(-1.f, -1.f, -1.f, -1.f));
        }
        s_row[t] = rowx;
    }
    __syncthreads();

    const float4* __restrict__ x4 = reinterpret_cast<const float4*>(x);
    float4* __restrict__ dst = reinterpret_cast<float4*>(out) + (size_t)rbase * (HID / 4);
    const float4 z = make_float4(0.f, 0.f, 0.f, 0.f);

    #pragma unroll
    for (int i = 0; i < RPB; i++) {
        const int rowx = s_row[i];
        float4 v = z;
        if (rowx >= 0) v = __ldg(&x4[(size_t)rowx * (HID / 4) + t]);
        __stcs(&dst[(size_t)i * (HID / 4) + t], v);
    }
}

// ---------------------------------------------------------------------------
extern "C" void kernel_launch(void* const* d_in, const int* in_sizes, int n_in,
                              void* d_out, int out_size) {
    const float* x   = (const float*)d_in[0];   // (8,2048,1024) f32
    const float* wts = (const float*)d_in[1];   // (8,2048,8) f32
    const int*   idx = (const int*)d_in[2];     // (8,2048,8) i32
    float* out = (float*)d_out;

    k_hist<<<NTOT / 256, 256>>>(idx);
    k_scan<<<NEXP, 128>>>(out);
    k_scatter<<<NTOT / 256, 256>>>(idx);
    dim3 g(NEXP, MAXTOK / RPB);
    k_gather<<<g, 256>>>(x, wts, out);
}

// round 17
// speedup vs baseline: 1.5253x; 1.0318x over previous
#include <cuda_runtime.h>

// Problem constants
#define NCHIP   8
#define SEQ     2048
#define TOPK    8
#define HID     1024
#define NEXP    64
#define MAXTOK  2560
#define NPC     (SEQ * TOPK)          // 16384 assignments per chip
#define NTOT    (NCHIP * NPC)         // 131072 assignments total
#define NROWS   (NEXP * MAXTOK)       // 163840 output rows
#define METAL   8
#define RPB     16                    // rows per gather block
#define NBLK    (NTOT / 256)          // 512 scan-ordered scatter blocks

// Output layout (flattened concat, float32):
#define DISP_ELEMS   ((size_t)NROWS * HID)          // 167772160
#define META_OFF     DISP_ELEMS
#define META_ELEMS   ((size_t)NROWS * METAL)        // 1310720
#define TPE_OFF      (META_OFF + META_ELEMS)        // 169082880

// Scratch (static device globals; no allocation allowed)
__device__ int g_bcnt[NBLK * NEXP];   // per-block per-expert counts (128KB)
__device__ int g_boff[NBLK * NEXP];   // exclusive scan of the above (128KB)
__device__ int g_total[NEXP];
__device__ int g_src[NROWS];

// ---------------------------------------------------------------------------
// Phase 1: per-BLOCK expert histograms. Per-warp counts via __match_any_sync
// into smem [8][64], then 64 threads sum across warps and write one coalesced
// 64-int row per block. Table is 8x smaller than per-warp granularity.
// grid = 512, block = 256.
// ---------------------------------------------------------------------------
__global__ void __launch_bounds__(256) k_hist(const int* __restrict__ idx) {
    __shared__ int cnt[8 * NEXP];
    const int t    = threadIdx.x;
    const int w    = t >> 5;
    const int lane = t & 31;

    cnt[t] = 0; cnt[t + 256] = 0;
    __syncthreads();

    const int e = idx[blockIdx.x * 256 + t];
    const unsigned m = __match_any_sync(0xffffffffu, e);
    if (lane == (__ffs(m) - 1)) cnt[w * NEXP + e] = __popc(m);
    __syncthreads();

    if (t < NEXP) {
        int s = 0;
        #pragma unroll
        for (int w2 = 0; w2 < 8; w2++) s += cnt[w2 * NEXP + t];
        g_bcnt[blockIdx.x * NEXP + t] = s;
    }
}

// ---------------------------------------------------------------------------
// Phase 2: per-expert exclusive scan over the 512 scan-ordered block counts.
// grid = 64 (one block per expert), block = 128 (4 values per thread).
// Also emits g_total and tokens_per_expert (value-cast float, flat order).
// ---------------------------------------------------------------------------
__global__ void __launch_bounds__(128) k_scan(float* __restrict__ out) {
    const int e = blockIdx.x;
    const int t = threadIdx.x;
    const int lane = t & 31, wid = t >> 5;

    int v[4];
    int sum = 0;
    #pragma unroll
    for (int i = 0; i < 4; i++) { v[i] = g_bcnt[(t * 4 + i) * NEXP + e]; sum += v[i]; }

    // inclusive warp scan of per-thread sums
    int s = sum;
    #pragma unroll
    for (int o = 1; o < 32; o <<= 1) {
        int u = __shfl_up_sync(0xffffffffu, s, o);
        if (lane >= o) s += u;
    }
    __shared__ int wsum[4];
    if (lane == 31) wsum[wid] = s;
    __syncthreads();
    int wpre = 0;
    #pragma unroll
    for (int k = 0; k < 4; k++) if (k < wid) wpre += wsum[k];

    int excl = wpre + s - sum;
    #pragma unroll
    for (int i = 0; i < 4; i++) { g_boff[(t * 4 + i) * NEXP + e] = excl; excl += v[i]; }

    if (t == 127) { g_total[e] = excl; out[TPE_OFF + e] = (float)excl; }
}

// ---------------------------------------------------------------------------
// Phase 3: scatter assignment ids into the row table. Recomputes per-warp
// counts (match_any), does the 8-warp intra-block exclusive scan in smem,
// then dest = e*MAXTOK + blockBase + intraBlockOff + intraWarpRank.
// Blocks/warps/lanes are all scan-ordered -> exact stable-argsort ranks.
// dest slots are unique; filled slots per expert are exactly [0, g_total[e]),
// so no -1 init pass. mode="drop" == dest bound. grid = 512, block = 256.
// ---------------------------------------------------------------------------
__global__ void __launch_bounds__(256) k_scatter(const int* __restrict__ idx) {
    __shared__ int cnt[8 * NEXP];
    __shared__ int off[8 * NEXP];
    const int t    = threadIdx.x;
    const int w    = t >> 5;
    const int lane = t & 31;

    cnt[t] = 0; cnt[t + 256] = 0;
    __syncthreads();

    const int a = blockIdx.x * 256 + t;
    const int e = idx[a];
    const unsigned m = __match_any_sync(0xffffffffu, e);
    const int rank = __popc(m & ((1u << lane) - 1u));
    if (lane == (__ffs(m) - 1)) cnt[w * NEXP + e] = __popc(m);
    __syncthreads();

    if (t < NEXP) {
        int r = 0;
        #pragma unroll
        for (int w2 = 0; w2 < 8; w2++) { off[w2 * NEXP + t] = r; r += cnt[w2 * NEXP + t]; }
    }
    __syncthreads();

    const int dest = e * MAXTOK + g_boff[blockIdx.x * NEXP + e] + off[w * NEXP + e] + rank;
    if (dest < NROWS) g_src[dest] = a;
}

// ---------------------------------------------------------------------------
// Phase 4: the big gather, MLP + locality optimized (unchanged from R16 —
// measured at the compulsory DRAM-traffic floor).
// Grid = (NEXP, MAXTOK/RPB) — expert-major block order so the concurrent wave
// covers the same slot range across all 64 experts; a token's 8 copies sit at
// near-identical slots, so x is DRAM-read once and L2-served 7x.
// Prologue resolves g_src for RPB rows + writes metadata; main loop issues
// 16 independent LDG.128s per thread. __stcs keeps the write stream from
// evicting x in L2.
// ---------------------------------------------------------------------------
__global__ void __launch_bounds__(256) k_gather(const float* __restrict__ x,
                                                const float* __restrict__ w,
                                                float* __restrict__ out) {
    __shared__ int s_row[RPB];          // x row index (c*SEQ+s), or -1 = empty

    const int e     = blockIdx.x;
    const int base  = blockIdx.y * RPB;
    const int rbase = e * MAXTOK + base;
    const int t     = threadIdx.x;

    if (t < RPB) {
        const int slot = base + t;
        const int r    = rbase + t;
        int rowx = -1;
        float4* mrow = reinterpret_cast<float4*>(out + META_OFF + (size_t)r * METAL);
        if (slot < g_total[e]) {
            const int a = g_src[r];
            const int c = a >> 14;
            const int n = a & (NPC - 1);
            const int s = n >> 3;
            const int k = n & 7;
            rowx = c * SEQ + s;
            const float wt = __ldg(&w[rowx * TOPK + k]);
            __stcs(mrow,     make_float4((float)c, (float)s, (float)k, (float)e));
            __stcs(mrow + 1, make_float4(wt, 0.f, 0.f, 0.f));
        } else {
            __stcs(mrow,     make_float4(-1.f, -1.f, -1.f, -1.f));
            __stcs(mrow + 1, make_float4(-1.f, -1.f, -1.f, -1.f));
        }
        s_row[t] = rowx;
    }
    __syncthreads();

    const float4* __restrict__ x4 = reinterpret_cast<const float4*>(x);
    float4* __restrict__ dst = reinterpret_cast<float4*>(out) + (size_t)rbase * (HID / 4);
    const float4 z = make_float4(0.f, 0.f, 0.f, 0.f);

    #pragma unroll
    for (int i = 0; i < RPB; i++) {
        const int rowx = s_row[i];
        float4 v = z;
        if (rowx >= 0) v = __ldg(&x4[(size_t)rowx * (HID / 4) + t]);
        __stcs(&dst[(size_t)i * (HID / 4) + t], v);
    }
}

// ---------------------------------------------------------------------------
extern "C" void kernel_launch(void* const* d_in, const int* in_sizes, int n_in,
                              void* d_out, int out_size) {
    const float* x   = (const float*)d_in[0];   // (8,2048,1024) f32
    const float* wts = (const float*)d_in[1];   // (8,2048,8) f32
    const int*   idx = (const int*)d_in[2];     // (8,2048,8) i32
    float* out = (float*)d_out;

    k_hist<<<NBLK, 256>>>(idx);
    k_scan<<<NEXP, 128>>>(out);
    k_scatter<<<NBLK, 256>>>(idx);
    dim3 g(NEXP, MAXTOK / RPB);
    k_gather<<<g, 256>>>(x, wts, out);
}